// round 1
// baseline (speedup 1.0000x reference)
#include <cuda_runtime.h>
#include <math.h>
#include <float.h>

#define B_   8
#define V_   4
#define N_   16384
#define CP_  256
#define BV_  (B_*V_)          // 32
#define TP_  32               // points per tile
#define TPB_ (N_/TP_)         // 512 tiles per (b,v)
#define NTILES_ (BV_*TPB_)    // 16384

// ---------------- scratch (static device globals; no allocations) -----------
__device__ float d_center[BV_*3];
__device__ float d_invdiam[BV_];
__device__ __align__(16) float d_gmax[BV_*CP_];
__device__ __align__(16) float d_gpart[BV_*CP_];
__device__ __align__(16) float d_local[(size_t)BV_*N_*CP_];   // 537 MB
__device__ float d_mw[BV_*N_];
__device__ float d_denom[BV_];

// signed-float atomic max (handles negatives and -0 correctly)
__device__ __forceinline__ void atomicMaxFloat(float* addr, float val) {
    if (__float_as_int(val) >= 0)
        atomicMax((int*)addr, __float_as_int(val));
    else
        atomicMin((unsigned int*)addr, __float_as_uint(val));
}

// ---------------- kernel A: per-(b,v) stats + init --------------------------
__global__ void __launch_bounds__(256) kA(const float* __restrict__ xyz,
                                          const float* __restrict__ masks) {
    int bv = blockIdx.x;
    int b  = bv >> 2;
    int tid = threadIdx.x;

    float s0=0.f, s1=0.f, s2=0.f, cnt=0.f;
    float mx0=-FLT_MAX, mx1=-FLT_MAX, mx2=-FLT_MAX;
    float mn0= FLT_MAX, mn1= FLT_MAX, mn2= FLT_MAX;

    const float* mrow = masks + (size_t)bv*N_;
    const float* x0r  = xyz + (size_t)(b*3+0)*N_;
    const float* x1r  = xyz + (size_t)(b*3+1)*N_;
    const float* x2r  = xyz + (size_t)(b*3+2)*N_;

    for (int n = tid; n < N_; n += 256) {
        float m = mrow[n];
        float a = x0r[n]*m, c = x1r[n]*m, e = x2r[n]*m;
        s0 += a; s1 += c; s2 += e; cnt += m;
        mx0 = fmaxf(mx0,a); mx1 = fmaxf(mx1,c); mx2 = fmaxf(mx2,e);
        mn0 = fminf(mn0,a); mn1 = fminf(mn1,c); mn2 = fminf(mn2,e);
    }

    __shared__ float rs[4][256];
    __shared__ float rx[3][256];
    __shared__ float rn[3][256];
    rs[0][tid]=s0; rs[1][tid]=s1; rs[2][tid]=s2; rs[3][tid]=cnt;
    rx[0][tid]=mx0; rx[1][tid]=mx1; rx[2][tid]=mx2;
    rn[0][tid]=mn0; rn[1][tid]=mn1; rn[2][tid]=mn2;
    __syncthreads();
    for (int s = 128; s > 0; s >>= 1) {
        if (tid < s) {
            #pragma unroll
            for (int q = 0; q < 4; q++) rs[q][tid] += rs[q][tid+s];
            #pragma unroll
            for (int q = 0; q < 3; q++) {
                rx[q][tid] = fmaxf(rx[q][tid], rx[q][tid+s]);
                rn[q][tid] = fminf(rn[q][tid], rn[q][tid+s]);
            }
        }
        __syncthreads();
    }
    if (tid == 0) {
        float valid = fmaxf(rs[3][0], 1.f);
        d_center[bv*3+0] = rs[0][0]/valid;
        d_center[bv*3+1] = rs[1][0]/valid;
        d_center[bv*3+2] = rs[2][0]/valid;
        float diam = fmaxf(fmaxf(rx[0][0]-rn[0][0], rx[1][0]-rn[1][0]),
                           rx[2][0]-rn[2][0]);
        if (diam == 0.f) diam = 1.f;
        d_invdiam[bv] = 1.f/diam;
        d_denom[bv]   = 0.f;
    }
    d_gmax[bv*CP_ + tid] = -FLT_MAX;   // init for atomicMax
}

// ---------------- kernel B: W1+LN+ReLU -> W2+LN -> local + global max -------
__global__ void __launch_bounds__(256) kB(const float* __restrict__ xyz,
    const float* __restrict__ W1, const float* __restrict__ b1,
    const float* __restrict__ g1, const float* __restrict__ be1,
    const float* __restrict__ W2, const float* __restrict__ b2,
    const float* __restrict__ g2, const float* __restrict__ be2)
{
    __shared__ float sx[TP_][3];
    __shared__ __align__(16) float sh[TP_][CP_];
    __shared__ float redS[8][8];
    __shared__ float redQ[8][8];
    __shared__ __align__(16) float scmax[4][CP_];

    int tile = blockIdx.x;
    int bv = tile / TPB_;
    int n0 = (tile % TPB_) * TP_;
    int b  = bv >> 2;
    int tid = threadIdx.x;
    int tc = tid & 63, tp = tid >> 6;
    int c0 = tc * 4;
    int lane = tid & 31, warp = tid >> 5;

    if (tid < 96) {
        int d = tid >> 5;          // 0..2
        int p = tid & 31;
        float xr = xyz[(size_t)(b*3+d)*N_ + n0 + p];
        sx[p][d] = (xr - d_center[bv*3+d]) * d_invdiam[bv];
    }
    __syncthreads();

    // ---- stage 1: y1 = norm_xyz @ W1 + b1 ----
    float4 w10 = *(const float4*)(W1 + 0*CP_ + c0);
    float4 w11 = *(const float4*)(W1 + 1*CP_ + c0);
    float4 w12 = *(const float4*)(W1 + 2*CP_ + c0);
    float4 vb1 = *(const float4*)(b1 + c0);
    float4 y[8];
    #pragma unroll
    for (int j = 0; j < 8; j++) {
        int p = tp*8 + j;
        float x0 = sx[p][0], x1 = sx[p][1], x2 = sx[p][2];
        y[j].x = vb1.x + x0*w10.x + x1*w11.x + x2*w12.x;
        y[j].y = vb1.y + x0*w10.y + x1*w11.y + x2*w12.y;
        y[j].z = vb1.z + x0*w10.z + x1*w11.z + x2*w12.z;
        y[j].w = vb1.w + x0*w10.w + x1*w11.w + x2*w12.w;
    }
    // LN1 reduction (64 threads = 2 warps per point-group)
    #pragma unroll
    for (int j = 0; j < 8; j++) {
        float s = y[j].x + y[j].y + y[j].z + y[j].w;
        float q = y[j].x*y[j].x + y[j].y*y[j].y + y[j].z*y[j].z + y[j].w*y[j].w;
        #pragma unroll
        for (int o = 16; o > 0; o >>= 1) {
            s += __shfl_xor_sync(0xffffffffu, s, o);
            q += __shfl_xor_sync(0xffffffffu, q, o);
        }
        if (lane == 0) { redS[warp][j] = s; redQ[warp][j] = q; }
    }
    __syncthreads();
    {
        float4 vg = *(const float4*)(g1 + c0);
        float4 ve = *(const float4*)(be1 + c0);
        #pragma unroll
        for (int j = 0; j < 8; j++) {
            float S = redS[2*tp][j] + redS[2*tp+1][j];
            float Q = redQ[2*tp][j] + redQ[2*tp+1][j];
            float mean = S * (1.f/CP_);
            float rstd = rsqrtf(Q*(1.f/CP_) - mean*mean + 1e-5f);
            float4 h;
            h.x = fmaxf((y[j].x-mean)*rstd*vg.x + ve.x, 0.f);
            h.y = fmaxf((y[j].y-mean)*rstd*vg.y + ve.y, 0.f);
            h.z = fmaxf((y[j].z-mean)*rstd*vg.z + ve.z, 0.f);
            h.w = fmaxf((y[j].w-mean)*rstd*vg.w + ve.w, 0.f);
            *(float4*)&sh[tp*8+j][c0] = h;
        }
    }
    __syncthreads();

    // ---- stage 2: y2 = h @ W2 + b2 (8pt x 4col register tile, k-unroll 4) --
    float4 acc[8];
    #pragma unroll
    for (int j = 0; j < 8; j++) acc[j] = make_float4(0.f,0.f,0.f,0.f);
    const float* w2p = W2 + c0;
    for (int k = 0; k < CP_; k += 4) {
        float4 wa = *(const float4*)(w2p + (size_t)(k+0)*CP_);
        float4 wb = *(const float4*)(w2p + (size_t)(k+1)*CP_);
        float4 wc = *(const float4*)(w2p + (size_t)(k+2)*CP_);
        float4 wd = *(const float4*)(w2p + (size_t)(k+3)*CP_);
        #pragma unroll
        for (int j = 0; j < 8; j++) {
            float4 h4 = *(const float4*)&sh[tp*8+j][k];
            acc[j].x += h4.x*wa.x; acc[j].y += h4.x*wa.y; acc[j].z += h4.x*wa.z; acc[j].w += h4.x*wa.w;
            acc[j].x += h4.y*wb.x; acc[j].y += h4.y*wb.y; acc[j].z += h4.y*wb.z; acc[j].w += h4.y*wb.w;
            acc[j].x += h4.z*wc.x; acc[j].y += h4.z*wc.y; acc[j].z += h4.z*wc.z; acc[j].w += h4.z*wc.w;
            acc[j].x += h4.w*wd.x; acc[j].y += h4.w*wd.y; acc[j].z += h4.w*wd.z; acc[j].w += h4.w*wd.w;
        }
    }
    {
        float4 vb2 = *(const float4*)(b2 + c0);
        #pragma unroll
        for (int j = 0; j < 8; j++) {
            acc[j].x += vb2.x; acc[j].y += vb2.y; acc[j].z += vb2.z; acc[j].w += vb2.w;
        }
    }
    // LN2 reduction
    #pragma unroll
    for (int j = 0; j < 8; j++) {
        float s = acc[j].x + acc[j].y + acc[j].z + acc[j].w;
        float q = acc[j].x*acc[j].x + acc[j].y*acc[j].y + acc[j].z*acc[j].z + acc[j].w*acc[j].w;
        #pragma unroll
        for (int o = 16; o > 0; o >>= 1) {
            s += __shfl_xor_sync(0xffffffffu, s, o);
            q += __shfl_xor_sync(0xffffffffu, q, o);
        }
        if (lane == 0) { redS[warp][j] = s; redQ[warp][j] = q; }
    }
    __syncthreads();
    {
        float4 vg = *(const float4*)(g2 + c0);
        float4 ve = *(const float4*)(be2 + c0);
        float4 cmax = make_float4(-FLT_MAX,-FLT_MAX,-FLT_MAX,-FLT_MAX);
        #pragma unroll
        for (int j = 0; j < 8; j++) {
            float S = redS[2*tp][j] + redS[2*tp+1][j];
            float Q = redQ[2*tp][j] + redQ[2*tp+1][j];
            float mean = S * (1.f/CP_);
            float rstd = rsqrtf(Q*(1.f/CP_) - mean*mean + 1e-5f);
            float4 lv;
            lv.x = (acc[j].x-mean)*rstd*vg.x + ve.x;
            lv.y = (acc[j].y-mean)*rstd*vg.y + ve.y;
            lv.z = (acc[j].z-mean)*rstd*vg.z + ve.z;
            lv.w = (acc[j].w-mean)*rstd*vg.w + ve.w;
            *(float4*)(d_local + ((size_t)(bv*N_ + n0) + tp*8 + j)*CP_ + c0) = lv;
            cmax.x = fmaxf(cmax.x, lv.x); cmax.y = fmaxf(cmax.y, lv.y);
            cmax.z = fmaxf(cmax.z, lv.z); cmax.w = fmaxf(cmax.w, lv.w);
        }
        *(float4*)&scmax[tp][c0] = cmax;
    }
    __syncthreads();
    {
        int c = tid;
        float m = fmaxf(fmaxf(scmax[0][c], scmax[1][c]),
                        fmaxf(scmax[2][c], scmax[3][c]));
        atomicMaxFloat(&d_gmax[bv*CP_ + c], m);
    }
}

// ---------------- kernel C: gpart = global_xyz @ W3[256:512] + b3 -----------
__global__ void __launch_bounds__(256) kC(const float* __restrict__ W3,
                                          const float* __restrict__ b3) {
    int bv = blockIdx.x;
    int c  = threadIdx.x;
    __shared__ float sg[CP_];
    sg[c] = d_gmax[bv*CP_ + c];
    __syncthreads();
    float acc = b3[c];
    const float* w = W3 + (size_t)256*CP_ + c;   // bottom half rows
    #pragma unroll 8
    for (int k = 0; k < CP_; k++) acc += sg[k] * w[(size_t)k*CP_];
    d_gpart[bv*CP_ + c] = acc;
}

// ---------------- kernel D: W3-top GEMM + LN + ReLU + W4 dot -> weights -----
__global__ void __launch_bounds__(256) kD(const float* __restrict__ masks,
    const float* __restrict__ W3, const float* __restrict__ g3,
    const float* __restrict__ be3, const float* __restrict__ W4)
{
    __shared__ __align__(16) float sh[TP_][CP_];
    __shared__ float redS[8][8];
    __shared__ float redQ[8][8];
    __shared__ float swgt[TP_];

    int tile = blockIdx.x;
    int bv = tile / TPB_;
    int n0 = (tile % TPB_) * TP_;
    int tid = threadIdx.x;
    int tc = tid & 63, tp = tid >> 6;
    int c0 = tc * 4;
    int lane = tid & 31, warp = tid >> 5;

    // cooperative coalesced load of the local tile (32x256 fp32 = 32KB)
    {
        const float4* src = (const float4*)(d_local + (size_t)(bv*N_ + n0)*CP_);
        float4* dst = (float4*)&sh[0][0];
        #pragma unroll
        for (int i = 0; i < 8; i++) dst[tid + 256*i] = src[tid + 256*i];
    }
    __syncthreads();

    float4 gp = *(const float4*)(d_gpart + bv*CP_ + c0);
    float4 acc[8];
    #pragma unroll
    for (int j = 0; j < 8; j++) acc[j] = gp;

    const float* w3p = W3 + c0;
    for (int k = 0; k < CP_; k += 4) {
        float4 wa = *(const float4*)(w3p + (size_t)(k+0)*CP_);
        float4 wb = *(const float4*)(w3p + (size_t)(k+1)*CP_);
        float4 wc = *(const float4*)(w3p + (size_t)(k+2)*CP_);
        float4 wd = *(const float4*)(w3p + (size_t)(k+3)*CP_);
        #pragma unroll
        for (int j = 0; j < 8; j++) {
            float4 h4 = *(const float4*)&sh[tp*8+j][k];
            acc[j].x += h4.x*wa.x; acc[j].y += h4.x*wa.y; acc[j].z += h4.x*wa.z; acc[j].w += h4.x*wa.w;
            acc[j].x += h4.y*wb.x; acc[j].y += h4.y*wb.y; acc[j].z += h4.y*wb.z; acc[j].w += h4.y*wb.w;
            acc[j].x += h4.z*wc.x; acc[j].y += h4.z*wc.y; acc[j].z += h4.z*wc.z; acc[j].w += h4.z*wc.w;
            acc[j].x += h4.w*wd.x; acc[j].y += h4.w*wd.y; acc[j].z += h4.w*wd.z; acc[j].w += h4.w*wd.w;
        }
    }

    // LN3 reduction
    #pragma unroll
    for (int j = 0; j < 8; j++) {
        float s = acc[j].x + acc[j].y + acc[j].z + acc[j].w;
        float q = acc[j].x*acc[j].x + acc[j].y*acc[j].y + acc[j].z*acc[j].z + acc[j].w*acc[j].w;
        #pragma unroll
        for (int o = 16; o > 0; o >>= 1) {
            s += __shfl_xor_sync(0xffffffffu, s, o);
            q += __shfl_xor_sync(0xffffffffu, q, o);
        }
        if (lane == 0) { redS[warp][j] = s; redQ[warp][j] = q; }
    }
    __syncthreads();

    float part[8];
    {
        float4 vg  = *(const float4*)(g3 + c0);
        float4 ve  = *(const float4*)(be3 + c0);
        float4 w4v = *(const float4*)(W4 + c0);
        #pragma unroll
        for (int j = 0; j < 8; j++) {
            float S = redS[2*tp][j] + redS[2*tp+1][j];
            float Q = redQ[2*tp][j] + redQ[2*tp+1][j];
            float mean = S * (1.f/CP_);
            float rstd = rsqrtf(Q*(1.f/CP_) - mean*mean + 1e-5f);
            float hx = fmaxf((acc[j].x-mean)*rstd*vg.x + ve.x, 0.f);
            float hy = fmaxf((acc[j].y-mean)*rstd*vg.y + ve.y, 0.f);
            float hz = fmaxf((acc[j].z-mean)*rstd*vg.z + ve.z, 0.f);
            float hw = fmaxf((acc[j].w-mean)*rstd*vg.w + ve.w, 0.f);
            part[j] = hx*w4v.x + hy*w4v.y + hz*w4v.z + hw*w4v.w;
        }
    }
    __syncthreads();   // protect redS reuse below

    // reduce W4 dot across the 64 threads of each point group
    #pragma unroll
    for (int j = 0; j < 8; j++) {
        float s = part[j];
        #pragma unroll
        for (int o = 16; o > 0; o >>= 1) s += __shfl_xor_sync(0xffffffffu, s, o);
        if (lane == 0) redS[warp][j] = s;
    }
    __syncthreads();

    if (tc == 0) {   // one thread per point group (tid 0,64,128,192)
        const float* mrow = masks + (size_t)bv*N_;
        #pragma unroll
        for (int j = 0; j < 8; j++) {
            float dot = redS[2*tp][j] + redS[2*tp+1][j];
            int n = n0 + tp*8 + j;
            float m = mrow[n];
            float w = 2.f * m / (1.f + expf(-dot));   // mask * sigmoid * 2
            d_mw[(size_t)bv*N_ + n] = w;
            swgt[tp*8+j] = w;
        }
    }
    __syncthreads();
    if (tid == 0) {
        float s = 0.f;
        #pragma unroll
        for (int p = 0; p < TP_; p++) s += swgt[p];
        atomicAdd(&d_denom[bv], s);
    }
}

// ---------------- kernel E: weighted pooling + epilogue ---------------------
__global__ void __launch_bounds__(256) kE(const float* __restrict__ feats,
                                          float* __restrict__ out) {
    int blk = blockIdx.x;        // b*CP_ + c
    int b = blk >> 8;
    int c = blk & 255;
    int tid = threadIdx.x;

    const float* f   = feats + (size_t)(b*CP_ + c)*N_;
    const float* mw0 = d_mw + (size_t)(b*4+0)*N_;
    const float* mw1 = d_mw + (size_t)(b*4+1)*N_;
    const float* mw2 = d_mw + (size_t)(b*4+2)*N_;
    const float* mw3 = d_mw + (size_t)(b*4+3)*N_;

    float a0=0.f, a1=0.f, a2=0.f, a3=0.f;
    for (int n = tid; n < N_; n += 256) {
        float fv = f[n];
        a0 += fv*mw0[n]; a1 += fv*mw1[n]; a2 += fv*mw2[n]; a3 += fv*mw3[n];
    }
    #pragma unroll
    for (int o = 16; o > 0; o >>= 1) {
        a0 += __shfl_xor_sync(0xffffffffu, a0, o);
        a1 += __shfl_xor_sync(0xffffffffu, a1, o);
        a2 += __shfl_xor_sync(0xffffffffu, a2, o);
        a3 += __shfl_xor_sync(0xffffffffu, a3, o);
    }
    __shared__ float sr[4][8];
    int lane = tid & 31, warp = tid >> 5;
    if (lane == 0) { sr[0][warp]=a0; sr[1][warp]=a1; sr[2][warp]=a2; sr[3][warp]=a3; }
    __syncthreads();
    if (tid < 4) {
        float p = 0.f;
        #pragma unroll
        for (int w = 0; w < 8; w++) p += sr[tid][w];
        int bvv = b*4 + tid;
        float den = fmaxf(d_denom[bvv], 1e-8f);
        out[(size_t)bvv*CP_ + c] = p/den + d_gmax[bvv*CP_ + c];
    }
}

// ---------------- launch ----------------------------------------------------
extern "C" void kernel_launch(void* const* d_in, const int* in_sizes, int n_in,
                              void* d_out, int out_size) {
    const float* xyz = (const float*)d_in[0];
    const float* pf  = (const float*)d_in[1];
    const float* pm  = (const float*)d_in[2];
    const float* W1  = (const float*)d_in[3];
    const float* b1  = (const float*)d_in[4];
    const float* g1  = (const float*)d_in[5];
    const float* be1 = (const float*)d_in[6];
    const float* W2  = (const float*)d_in[7];
    const float* b2  = (const float*)d_in[8];
    const float* g2  = (const float*)d_in[9];
    const float* be2 = (const float*)d_in[10];
    const float* W3  = (const float*)d_in[11];
    const float* b3  = (const float*)d_in[12];
    const float* g3  = (const float*)d_in[13];
    const float* be3 = (const float*)d_in[14];
    const float* W4  = (const float*)d_in[15];
    float* out = (float*)d_out;

    kA<<<BV_, 256>>>(xyz, pm);
    kB<<<NTILES_, 256>>>(xyz, W1, b1, g1, be1, W2, b2, g2, be2);
    kC<<<BV_, 256>>>(W3, b3);
    kD<<<NTILES_, 256>>>(pm, W3, g3, be3, W4);
    kE<<<B_*CP_, 256>>>(pf, out);
}

// round 2
// speedup vs baseline: 1.0006x; 1.0006x over previous
#include <cuda_runtime.h>
#include <math.h>
#include <float.h>

#define B_   8
#define V_   4
#define N_   16384
#define CP_  256
#define BV_  (B_*V_)          // 32
#define TP_  32               // points per tile
#define TPB_ (N_/TP_)         // 512 tiles per (b,v)
#define NTILES_ (BV_*TPB_)    // 16384

// ---------------- scratch (static device globals; no allocations) -----------
__device__ float d_center[BV_*3];
__device__ float d_invdiam[BV_];
__device__ __align__(16) float d_gmax[BV_*CP_];
__device__ __align__(16) float d_gpart[BV_*CP_];
__device__ __align__(16) float d_local[(size_t)BV_*N_*CP_];   // 537 MB
__device__ float d_mw[BV_*N_];
__device__ float d_denom[BV_];

// signed-float atomic max (handles negatives and -0 correctly)
__device__ __forceinline__ void atomicMaxFloat(float* addr, float val) {
    if (__float_as_int(val) >= 0)
        atomicMax((int*)addr, __float_as_int(val));
    else
        atomicMin((unsigned int*)addr, __float_as_uint(val));
}

// ---------------- kernel A: per-(b,v) stats + init --------------------------
__global__ void __launch_bounds__(256) kA(const float* __restrict__ xyz,
                                          const float* __restrict__ masks) {
    int bv = blockIdx.x;
    int b  = bv >> 2;
    int tid = threadIdx.x;

    float s0=0.f, s1=0.f, s2=0.f, cnt=0.f;
    float mx0=-FLT_MAX, mx1=-FLT_MAX, mx2=-FLT_MAX;
    float mn0= FLT_MAX, mn1= FLT_MAX, mn2= FLT_MAX;

    const float* mrow = masks + (size_t)bv*N_;
    const float* x0r  = xyz + (size_t)(b*3+0)*N_;
    const float* x1r  = xyz + (size_t)(b*3+1)*N_;
    const float* x2r  = xyz + (size_t)(b*3+2)*N_;

    for (int n = tid; n < N_; n += 256) {
        float m = mrow[n];
        float a = x0r[n]*m, c = x1r[n]*m, e = x2r[n]*m;
        s0 += a; s1 += c; s2 += e; cnt += m;
        mx0 = fmaxf(mx0,a); mx1 = fmaxf(mx1,c); mx2 = fmaxf(mx2,e);
        mn0 = fminf(mn0,a); mn1 = fminf(mn1,c); mn2 = fminf(mn2,e);
    }

    __shared__ float rs[4][256];
    __shared__ float rx[3][256];
    __shared__ float rn[3][256];
    rs[0][tid]=s0; rs[1][tid]=s1; rs[2][tid]=s2; rs[3][tid]=cnt;
    rx[0][tid]=mx0; rx[1][tid]=mx1; rx[2][tid]=mx2;
    rn[0][tid]=mn0; rn[1][tid]=mn1; rn[2][tid]=mn2;
    __syncthreads();
    for (int s = 128; s > 0; s >>= 1) {
        if (tid < s) {
            #pragma unroll
            for (int q = 0; q < 4; q++) rs[q][tid] += rs[q][tid+s];
            #pragma unroll
            for (int q = 0; q < 3; q++) {
                rx[q][tid] = fmaxf(rx[q][tid], rx[q][tid+s]);
                rn[q][tid] = fminf(rn[q][tid], rn[q][tid+s]);
            }
        }
        __syncthreads();
    }
    if (tid == 0) {
        float valid = fmaxf(rs[3][0], 1.f);
        d_center[bv*3+0] = rs[0][0]/valid;
        d_center[bv*3+1] = rs[1][0]/valid;
        d_center[bv*3+2] = rs[2][0]/valid;
        float diam = fmaxf(fmaxf(rx[0][0]-rn[0][0], rx[1][0]-rn[1][0]),
                           rx[2][0]-rn[2][0]);
        if (diam == 0.f) diam = 1.f;
        d_invdiam[bv] = 1.f/diam;
        d_denom[bv]   = 0.f;
    }
    d_gmax[bv*CP_ + tid] = -FLT_MAX;   // init for atomicMax
}

// ---------------- kernel B: W1+LN+ReLU -> W2+LN -> local + global max -------
__global__ void __launch_bounds__(256) kB(const float* __restrict__ xyz,
    const float* __restrict__ W1, const float* __restrict__ b1,
    const float* __restrict__ g1, const float* __restrict__ be1,
    const float* __restrict__ W2, const float* __restrict__ b2,
    const float* __restrict__ g2, const float* __restrict__ be2)
{
    __shared__ float sx[TP_][3];
    __shared__ __align__(16) float sh[TP_][CP_];
    __shared__ float redS[8][8];
    __shared__ float redQ[8][8];
    __shared__ __align__(16) float scmax[4][CP_];

    int tile = blockIdx.x;
    int bv = tile / TPB_;
    int n0 = (tile % TPB_) * TP_;
    int b  = bv >> 2;
    int tid = threadIdx.x;
    int tc = tid & 63, tp = tid >> 6;
    int c0 = tc * 4;
    int lane = tid & 31, warp = tid >> 5;

    if (tid < 96) {
        int d = tid >> 5;          // 0..2
        int p = tid & 31;
        float xr = xyz[(size_t)(b*3+d)*N_ + n0 + p];
        sx[p][d] = (xr - d_center[bv*3+d]) * d_invdiam[bv];
    }
    __syncthreads();

    // ---- stage 1: y1 = norm_xyz @ W1 + b1 ----
    float4 w10 = *(const float4*)(W1 + 0*CP_ + c0);
    float4 w11 = *(const float4*)(W1 + 1*CP_ + c0);
    float4 w12 = *(const float4*)(W1 + 2*CP_ + c0);
    float4 vb1 = *(const float4*)(b1 + c0);
    float4 y[8];
    #pragma unroll
    for (int j = 0; j < 8; j++) {
        int p = tp*8 + j;
        float x0 = sx[p][0], x1 = sx[p][1], x2 = sx[p][2];
        y[j].x = vb1.x + x0*w10.x + x1*w11.x + x2*w12.x;
        y[j].y = vb1.y + x0*w10.y + x1*w11.y + x2*w12.y;
        y[j].z = vb1.z + x0*w10.z + x1*w11.z + x2*w12.z;
        y[j].w = vb1.w + x0*w10.w + x1*w11.w + x2*w12.w;
    }
    // LN1 reduction (64 threads = 2 warps per point-group)
    #pragma unroll
    for (int j = 0; j < 8; j++) {
        float s = y[j].x + y[j].y + y[j].z + y[j].w;
        float q = y[j].x*y[j].x + y[j].y*y[j].y + y[j].z*y[j].z + y[j].w*y[j].w;
        #pragma unroll
        for (int o = 16; o > 0; o >>= 1) {
            s += __shfl_xor_sync(0xffffffffu, s, o);
            q += __shfl_xor_sync(0xffffffffu, q, o);
        }
        if (lane == 0) { redS[warp][j] = s; redQ[warp][j] = q; }
    }
    __syncthreads();
    {
        float4 vg = *(const float4*)(g1 + c0);
        float4 ve = *(const float4*)(be1 + c0);
        #pragma unroll
        for (int j = 0; j < 8; j++) {
            float S = redS[2*tp][j] + redS[2*tp+1][j];
            float Q = redQ[2*tp][j] + redQ[2*tp+1][j];
            float mean = S * (1.f/CP_);
            float rstd = rsqrtf(Q*(1.f/CP_) - mean*mean + 1e-5f);
            float4 h;
            h.x = fmaxf((y[j].x-mean)*rstd*vg.x + ve.x, 0.f);
            h.y = fmaxf((y[j].y-mean)*rstd*vg.y + ve.y, 0.f);
            h.z = fmaxf((y[j].z-mean)*rstd*vg.z + ve.z, 0.f);
            h.w = fmaxf((y[j].w-mean)*rstd*vg.w + ve.w, 0.f);
            *(float4*)&sh[tp*8+j][c0] = h;
        }
    }
    __syncthreads();

    // ---- stage 2: y2 = h @ W2 + b2 (8pt x 4col register tile, k-unroll 4) --
    float4 acc[8];
    #pragma unroll
    for (int j = 0; j < 8; j++) acc[j] = make_float4(0.f,0.f,0.f,0.f);
    const float* w2p = W2 + c0;
    for (int k = 0; k < CP_; k += 4) {
        float4 wa = *(const float4*)(w2p + (size_t)(k+0)*CP_);
        float4 wb = *(const float4*)(w2p + (size_t)(k+1)*CP_);
        float4 wc = *(const float4*)(w2p + (size_t)(k+2)*CP_);
        float4 wd = *(const float4*)(w2p + (size_t)(k+3)*CP_);
        #pragma unroll
        for (int j = 0; j < 8; j++) {
            float4 h4 = *(const float4*)&sh[tp*8+j][k];
            acc[j].x += h4.x*wa.x; acc[j].y += h4.x*wa.y; acc[j].z += h4.x*wa.z; acc[j].w += h4.x*wa.w;
            acc[j].x += h4.y*wb.x; acc[j].y += h4.y*wb.y; acc[j].z += h4.y*wb.z; acc[j].w += h4.y*wb.w;
            acc[j].x += h4.z*wc.x; acc[j].y += h4.z*wc.y; acc[j].z += h4.z*wc.z; acc[j].w += h4.z*wc.w;
            acc[j].x += h4.w*wd.x; acc[j].y += h4.w*wd.y; acc[j].z += h4.w*wd.z; acc[j].w += h4.w*wd.w;
        }
    }
    {
        float4 vb2 = *(const float4*)(b2 + c0);
        #pragma unroll
        for (int j = 0; j < 8; j++) {
            acc[j].x += vb2.x; acc[j].y += vb2.y; acc[j].z += vb2.z; acc[j].w += vb2.w;
        }
    }
    // LN2 reduction
    #pragma unroll
    for (int j = 0; j < 8; j++) {
        float s = acc[j].x + acc[j].y + acc[j].z + acc[j].w;
        float q = acc[j].x*acc[j].x + acc[j].y*acc[j].y + acc[j].z*acc[j].z + acc[j].w*acc[j].w;
        #pragma unroll
        for (int o = 16; o > 0; o >>= 1) {
            s += __shfl_xor_sync(0xffffffffu, s, o);
            q += __shfl_xor_sync(0xffffffffu, q, o);
        }
        if (lane == 0) { redS[warp][j] = s; redQ[warp][j] = q; }
    }
    __syncthreads();
    {
        float4 vg = *(const float4*)(g2 + c0);
        float4 ve = *(const float4*)(be2 + c0);
        float4 cmax = make_float4(-FLT_MAX,-FLT_MAX,-FLT_MAX,-FLT_MAX);
        #pragma unroll
        for (int j = 0; j < 8; j++) {
            float S = redS[2*tp][j] + redS[2*tp+1][j];
            float Q = redQ[2*tp][j] + redQ[2*tp+1][j];
            float mean = S * (1.f/CP_);
            float rstd = rsqrtf(Q*(1.f/CP_) - mean*mean + 1e-5f);
            float4 lv;
            lv.x = (acc[j].x-mean)*rstd*vg.x + ve.x;
            lv.y = (acc[j].y-mean)*rstd*vg.y + ve.y;
            lv.z = (acc[j].z-mean)*rstd*vg.z + ve.z;
            lv.w = (acc[j].w-mean)*rstd*vg.w + ve.w;
            *(float4*)(d_local + ((size_t)(bv*N_ + n0) + tp*8 + j)*CP_ + c0) = lv;
            cmax.x = fmaxf(cmax.x, lv.x); cmax.y = fmaxf(cmax.y, lv.y);
            cmax.z = fmaxf(cmax.z, lv.z); cmax.w = fmaxf(cmax.w, lv.w);
        }
        *(float4*)&scmax[tp][c0] = cmax;
    }
    __syncthreads();
    {
        int c = tid;
        float m = fmaxf(fmaxf(scmax[0][c], scmax[1][c]),
                        fmaxf(scmax[2][c], scmax[3][c]));
        atomicMaxFloat(&d_gmax[bv*CP_ + c], m);
    }
}

// ---------------- kernel C: gpart = global_xyz @ W3[256:512] + b3 -----------
__global__ void __launch_bounds__(256) kC(const float* __restrict__ W3,
                                          const float* __restrict__ b3) {
    int bv = blockIdx.x;
    int c  = threadIdx.x;
    __shared__ float sg[CP_];
    sg[c] = d_gmax[bv*CP_ + c];
    __syncthreads();
    float acc = b3[c];
    const float* w = W3 + (size_t)256*CP_ + c;   // bottom half rows
    #pragma unroll 8
    for (int k = 0; k < CP_; k++) acc += sg[k] * w[(size_t)k*CP_];
    d_gpart[bv*CP_ + c] = acc;
}

// ---------------- kernel D: W3-top GEMM + LN + ReLU + W4 dot -> weights -----
__global__ void __launch_bounds__(256) kD(const float* __restrict__ masks,
    const float* __restrict__ W3, const float* __restrict__ g3,
    const float* __restrict__ be3, const float* __restrict__ W4)
{
    __shared__ __align__(16) float sh[TP_][CP_];
    __shared__ float redS[8][8];
    __shared__ float redQ[8][8];
    __shared__ float swgt[TP_];

    int tile = blockIdx.x;
    int bv = tile / TPB_;
    int n0 = (tile % TPB_) * TP_;
    int tid = threadIdx.x;
    int tc = tid & 63, tp = tid >> 6;
    int c0 = tc * 4;
    int lane = tid & 31, warp = tid >> 5;

    // cooperative coalesced load of the local tile (32x256 fp32 = 32KB)
    {
        const float4* src = (const float4*)(d_local + (size_t)(bv*N_ + n0)*CP_);
        float4* dst = (float4*)&sh[0][0];
        #pragma unroll
        for (int i = 0; i < 8; i++) dst[tid + 256*i] = src[tid + 256*i];
    }
    __syncthreads();

    float4 gp = *(const float4*)(d_gpart + bv*CP_ + c0);
    float4 acc[8];
    #pragma unroll
    for (int j = 0; j < 8; j++) acc[j] = gp;

    const float* w3p = W3 + c0;
    for (int k = 0; k < CP_; k += 4) {
        float4 wa = *(const float4*)(w3p + (size_t)(k+0)*CP_);
        float4 wb = *(const float4*)(w3p + (size_t)(k+1)*CP_);
        float4 wc = *(const float4*)(w3p + (size_t)(k+2)*CP_);
        float4 wd = *(const float4*)(w3p + (size_t)(k+3)*CP_);
        #pragma unroll
        for (int j = 0; j < 8; j++) {
            float4 h4 = *(const float4*)&sh[tp*8+j][k];
            acc[j].x += h4.x*wa.x; acc[j].y += h4.x*wa.y; acc[j].z += h4.x*wa.z; acc[j].w += h4.x*wa.w;
            acc[j].x += h4.y*wb.x; acc[j].y += h4.y*wb.y; acc[j].z += h4.y*wb.z; acc[j].w += h4.y*wb.w;
            acc[j].x += h4.z*wc.x; acc[j].y += h4.z*wc.y; acc[j].z += h4.z*wc.z; acc[j].w += h4.z*wc.w;
            acc[j].x += h4.w*wd.x; acc[j].y += h4.w*wd.y; acc[j].z += h4.w*wd.z; acc[j].w += h4.w*wd.w;
        }
    }

    // LN3 reduction
    #pragma unroll
    for (int j = 0; j < 8; j++) {
        float s = acc[j].x + acc[j].y + acc[j].z + acc[j].w;
        float q = acc[j].x*acc[j].x + acc[j].y*acc[j].y + acc[j].z*acc[j].z + acc[j].w*acc[j].w;
        #pragma unroll
        for (int o = 16; o > 0; o >>= 1) {
            s += __shfl_xor_sync(0xffffffffu, s, o);
            q += __shfl_xor_sync(0xffffffffu, q, o);
        }
        if (lane == 0) { redS[warp][j] = s; redQ[warp][j] = q; }
    }
    __syncthreads();

    float part[8];
    {
        float4 vg  = *(const float4*)(g3 + c0);
        float4 ve  = *(const float4*)(be3 + c0);
        float4 w4v = *(const float4*)(W4 + c0);
        #pragma unroll
        for (int j = 0; j < 8; j++) {
            float S = redS[2*tp][j] + redS[2*tp+1][j];
            float Q = redQ[2*tp][j] + redQ[2*tp+1][j];
            float mean = S * (1.f/CP_);
            float rstd = rsqrtf(Q*(1.f/CP_) - mean*mean + 1e-5f);
            float hx = fmaxf((acc[j].x-mean)*rstd*vg.x + ve.x, 0.f);
            float hy = fmaxf((acc[j].y-mean)*rstd*vg.y + ve.y, 0.f);
            float hz = fmaxf((acc[j].z-mean)*rstd*vg.z + ve.z, 0.f);
            float hw = fmaxf((acc[j].w-mean)*rstd*vg.w + ve.w, 0.f);
            part[j] = hx*w4v.x + hy*w4v.y + hz*w4v.z + hw*w4v.w;
        }
    }
    __syncthreads();   // protect redS reuse below

    // reduce W4 dot across the 64 threads of each point group
    #pragma unroll
    for (int j = 0; j < 8; j++) {
        float s = part[j];
        #pragma unroll
        for (int o = 16; o > 0; o >>= 1) s += __shfl_xor_sync(0xffffffffu, s, o);
        if (lane == 0) redS[warp][j] = s;
    }
    __syncthreads();

    if (tc == 0) {   // one thread per point group (tid 0,64,128,192)
        const float* mrow = masks + (size_t)bv*N_;
        #pragma unroll
        for (int j = 0; j < 8; j++) {
            float dot = redS[2*tp][j] + redS[2*tp+1][j];
            int n = n0 + tp*8 + j;
            float m = mrow[n];
            float w = 2.f * m / (1.f + expf(-dot));   // mask * sigmoid * 2
            d_mw[(size_t)bv*N_ + n] = w;
            swgt[tp*8+j] = w;
        }
    }
    __syncthreads();
    if (tid == 0) {
        float s = 0.f;
        #pragma unroll
        for (int p = 0; p < TP_; p++) s += swgt[p];
        atomicAdd(&d_denom[bv], s);
    }
}

// ---------------- kernel E: weighted pooling + epilogue ---------------------
__global__ void __launch_bounds__(256) kE(const float* __restrict__ feats,
                                          float* __restrict__ out) {
    int blk = blockIdx.x;        // b*CP_ + c
    int b = blk >> 8;
    int c = blk & 255;
    int tid = threadIdx.x;

    const float* f   = feats + (size_t)(b*CP_ + c)*N_;
    const float* mw0 = d_mw + (size_t)(b*4+0)*N_;
    const float* mw1 = d_mw + (size_t)(b*4+1)*N_;
    const float* mw2 = d_mw + (size_t)(b*4+2)*N_;
    const float* mw3 = d_mw + (size_t)(b*4+3)*N_;

    float a0=0.f, a1=0.f, a2=0.f, a3=0.f;
    for (int n = tid; n < N_; n += 256) {
        float fv = f[n];
        a0 += fv*mw0[n]; a1 += fv*mw1[n]; a2 += fv*mw2[n]; a3 += fv*mw3[n];
    }
    #pragma unroll
    for (int o = 16; o > 0; o >>= 1) {
        a0 += __shfl_xor_sync(0xffffffffu, a0, o);
        a1 += __shfl_xor_sync(0xffffffffu, a1, o);
        a2 += __shfl_xor_sync(0xffffffffu, a2, o);
        a3 += __shfl_xor_sync(0xffffffffu, a3, o);
    }
    __shared__ float sr[4][8];
    int lane = tid & 31, warp = tid >> 5;
    if (lane == 0) { sr[0][warp]=a0; sr[1][warp]=a1; sr[2][warp]=a2; sr[3][warp]=a3; }
    __syncthreads();
    if (tid < 4) {
        float p = 0.f;
        #pragma unroll
        for (int w = 0; w < 8; w++) p += sr[tid][w];
        int bvv = b*4 + tid;
        float den = fmaxf(d_denom[bvv], 1e-8f);
        out[(size_t)bvv*CP_ + c] = p/den + d_gmax[bvv*CP_ + c];
    }
}

// ---------------- launch ----------------------------------------------------
extern "C" void kernel_launch(void* const* d_in, const int* in_sizes, int n_in,
                              void* d_out, int out_size) {
    const float* xyz = (const float*)d_in[0];
    const float* pf  = (const float*)d_in[1];
    const float* pm  = (const float*)d_in[2];
    const float* W1  = (const float*)d_in[3];
    const float* b1  = (const float*)d_in[4];
    const float* g1  = (const float*)d_in[5];
    const float* be1 = (const float*)d_in[6];
    const float* W2  = (const float*)d_in[7];
    const float* b2  = (const float*)d_in[8];
    const float* g2  = (const float*)d_in[9];
    const float* be2 = (const float*)d_in[10];
    const float* W3  = (const float*)d_in[11];
    const float* b3  = (const float*)d_in[12];
    const float* g3  = (const float*)d_in[13];
    const float* be3 = (const float*)d_in[14];
    const float* W4  = (const float*)d_in[15];
    float* out = (float*)d_out;

    kA<<<BV_, 256>>>(xyz, pm);
    kB<<<NTILES_, 256>>>(xyz, W1, b1, g1, be1, W2, b2, g2, be2);
    kC<<<BV_, 256>>>(W3, b3);
    kD<<<NTILES_, 256>>>(pm, W3, g3, be3, W4);
    kE<<<B_*CP_, 256>>>(pf, out);
}

// round 3
// speedup vs baseline: 1.0010x; 1.0004x over previous
#include <cuda_runtime.h>
#include <math.h>
#include <float.h>

#define B_   8
#define V_   4
#define N_   16384
#define CP_  256
#define BV_  (B_*V_)          // 32
#define TP_  32               // points per tile
#define TPB_ (N_/TP_)         // 512 tiles per (b,v)
#define NTILES_ (BV_*TPB_)    // 16384

// ---------------- scratch (static device globals; no allocations) -----------
__device__ float d_center[BV_*3];
__device__ float d_invdiam[BV_];
__device__ __align__(16) float d_gmax[BV_*CP_];
__device__ __align__(16) float d_gpart[BV_*CP_];
__device__ __align__(16) float d_local[(size_t)BV_*N_*CP_];   // 537 MB
__device__ float d_mw[BV_*N_];
__device__ float d_denom[BV_];

// signed-float atomic max (handles negatives and -0 correctly)
__device__ __forceinline__ void atomicMaxFloat(float* addr, float val) {
    if (__float_as_int(val) >= 0)
        atomicMax((int*)addr, __float_as_int(val));
    else
        atomicMin((unsigned int*)addr, __float_as_uint(val));
}

// ---------------- kernel A: per-(b,v) stats + init --------------------------
__global__ void __launch_bounds__(256) kA(const float* __restrict__ xyz,
                                          const float* __restrict__ masks) {
    int bv = blockIdx.x;
    int b  = bv >> 2;
    int tid = threadIdx.x;

    float s0=0.f, s1=0.f, s2=0.f, cnt=0.f;
    float mx0=-FLT_MAX, mx1=-FLT_MAX, mx2=-FLT_MAX;
    float mn0= FLT_MAX, mn1= FLT_MAX, mn2= FLT_MAX;

    const float* mrow = masks + (size_t)bv*N_;
    const float* x0r  = xyz + (size_t)(b*3+0)*N_;
    const float* x1r  = xyz + (size_t)(b*3+1)*N_;
    const float* x2r  = xyz + (size_t)(b*3+2)*N_;

    for (int n = tid; n < N_; n += 256) {
        float m = mrow[n];
        float a = x0r[n]*m, c = x1r[n]*m, e = x2r[n]*m;
        s0 += a; s1 += c; s2 += e; cnt += m;
        mx0 = fmaxf(mx0,a); mx1 = fmaxf(mx1,c); mx2 = fmaxf(mx2,e);
        mn0 = fminf(mn0,a); mn1 = fminf(mn1,c); mn2 = fminf(mn2,e);
    }

    __shared__ float rs[4][256];
    __shared__ float rx[3][256];
    __shared__ float rn[3][256];
    rs[0][tid]=s0; rs[1][tid]=s1; rs[2][tid]=s2; rs[3][tid]=cnt;
    rx[0][tid]=mx0; rx[1][tid]=mx1; rx[2][tid]=mx2;
    rn[0][tid]=mn0; rn[1][tid]=mn1; rn[2][tid]=mn2;
    __syncthreads();
    for (int s = 128; s > 0; s >>= 1) {
        if (tid < s) {
            #pragma unroll
            for (int q = 0; q < 4; q++) rs[q][tid] += rs[q][tid+s];
            #pragma unroll
            for (int q = 0; q < 3; q++) {
                rx[q][tid] = fmaxf(rx[q][tid], rx[q][tid+s]);
                rn[q][tid] = fminf(rn[q][tid], rn[q][tid+s]);
            }
        }
        __syncthreads();
    }
    if (tid == 0) {
        float valid = fmaxf(rs[3][0], 1.f);
        d_center[bv*3+0] = rs[0][0]/valid;
        d_center[bv*3+1] = rs[1][0]/valid;
        d_center[bv*3+2] = rs[2][0]/valid;
        float diam = fmaxf(fmaxf(rx[0][0]-rn[0][0], rx[1][0]-rn[1][0]),
                           rx[2][0]-rn[2][0]);
        if (diam == 0.f) diam = 1.f;
        d_invdiam[bv] = 1.f/diam;
        d_denom[bv]   = 0.f;
    }
    d_gmax[bv*CP_ + tid] = -FLT_MAX;   // init for atomicMax
}

// ---------------- kernel B: W1+LN+ReLU -> W2+LN -> local + global max -------
__global__ void __launch_bounds__(256) kB(const float* __restrict__ xyz,
    const float* __restrict__ W1, const float* __restrict__ b1,
    const float* __restrict__ g1, const float* __restrict__ be1,
    const float* __restrict__ W2, const float* __restrict__ b2,
    const float* __restrict__ g2, const float* __restrict__ be2)
{
    __shared__ float sx[TP_][3];
    __shared__ __align__(16) float sh[TP_][CP_];
    __shared__ float redS[8][8];
    __shared__ float redQ[8][8];
    __shared__ __align__(16) float scmax[4][CP_];

    int tile = blockIdx.x;
    int bv = tile / TPB_;
    int n0 = (tile % TPB_) * TP_;
    int b  = bv >> 2;
    int tid = threadIdx.x;
    int tc = tid & 63, tp = tid >> 6;
    int c0 = tc * 4;
    int lane = tid & 31, warp = tid >> 5;

    if (tid < 96) {
        int d = tid >> 5;          // 0..2
        int p = tid & 31;
        float xr = xyz[(size_t)(b*3+d)*N_ + n0 + p];
        sx[p][d] = (xr - d_center[bv*3+d]) * d_invdiam[bv];
    }
    __syncthreads();

    // ---- stage 1: y1 = norm_xyz @ W1 + b1 ----
    float4 w10 = *(const float4*)(W1 + 0*CP_ + c0);
    float4 w11 = *(const float4*)(W1 + 1*CP_ + c0);
    float4 w12 = *(const float4*)(W1 + 2*CP_ + c0);
    float4 vb1 = *(const float4*)(b1 + c0);
    float4 y[8];
    #pragma unroll
    for (int j = 0; j < 8; j++) {
        int p = tp*8 + j;
        float x0 = sx[p][0], x1 = sx[p][1], x2 = sx[p][2];
        y[j].x = vb1.x + x0*w10.x + x1*w11.x + x2*w12.x;
        y[j].y = vb1.y + x0*w10.y + x1*w11.y + x2*w12.y;
        y[j].z = vb1.z + x0*w10.z + x1*w11.z + x2*w12.z;
        y[j].w = vb1.w + x0*w10.w + x1*w11.w + x2*w12.w;
    }
    // LN1 reduction (64 threads = 2 warps per point-group)
    #pragma unroll
    for (int j = 0; j < 8; j++) {
        float s = y[j].x + y[j].y + y[j].z + y[j].w;
        float q = y[j].x*y[j].x + y[j].y*y[j].y + y[j].z*y[j].z + y[j].w*y[j].w;
        #pragma unroll
        for (int o = 16; o > 0; o >>= 1) {
            s += __shfl_xor_sync(0xffffffffu, s, o);
            q += __shfl_xor_sync(0xffffffffu, q, o);
        }
        if (lane == 0) { redS[warp][j] = s; redQ[warp][j] = q; }
    }
    __syncthreads();
    {
        float4 vg = *(const float4*)(g1 + c0);
        float4 ve = *(const float4*)(be1 + c0);
        #pragma unroll
        for (int j = 0; j < 8; j++) {
            float S = redS[2*tp][j] + redS[2*tp+1][j];
            float Q = redQ[2*tp][j] + redQ[2*tp+1][j];
            float mean = S * (1.f/CP_);
            float rstd = rsqrtf(Q*(1.f/CP_) - mean*mean + 1e-5f);
            float4 h;
            h.x = fmaxf((y[j].x-mean)*rstd*vg.x + ve.x, 0.f);
            h.y = fmaxf((y[j].y-mean)*rstd*vg.y + ve.y, 0.f);
            h.z = fmaxf((y[j].z-mean)*rstd*vg.z + ve.z, 0.f);
            h.w = fmaxf((y[j].w-mean)*rstd*vg.w + ve.w, 0.f);
            *(float4*)&sh[tp*8+j][c0] = h;
        }
    }
    __syncthreads();

    // ---- stage 2: y2 = h @ W2 + b2 (8pt x 4col register tile, k-unroll 4) --
    float4 acc[8];
    #pragma unroll
    for (int j = 0; j < 8; j++) acc[j] = make_float4(0.f,0.f,0.f,0.f);
    const float* w2p = W2 + c0;
    for (int k = 0; k < CP_; k += 4) {
        float4 wa = *(const float4*)(w2p + (size_t)(k+0)*CP_);
        float4 wb = *(const float4*)(w2p + (size_t)(k+1)*CP_);
        float4 wc = *(const float4*)(w2p + (size_t)(k+2)*CP_);
        float4 wd = *(const float4*)(w2p + (size_t)(k+3)*CP_);
        #pragma unroll
        for (int j = 0; j < 8; j++) {
            float4 h4 = *(const float4*)&sh[tp*8+j][k];
            acc[j].x += h4.x*wa.x; acc[j].y += h4.x*wa.y; acc[j].z += h4.x*wa.z; acc[j].w += h4.x*wa.w;
            acc[j].x += h4.y*wb.x; acc[j].y += h4.y*wb.y; acc[j].z += h4.y*wb.z; acc[j].w += h4.y*wb.w;
            acc[j].x += h4.z*wc.x; acc[j].y += h4.z*wc.y; acc[j].z += h4.z*wc.z; acc[j].w += h4.z*wc.w;
            acc[j].x += h4.w*wd.x; acc[j].y += h4.w*wd.y; acc[j].z += h4.w*wd.z; acc[j].w += h4.w*wd.w;
        }
    }
    {
        float4 vb2 = *(const float4*)(b2 + c0);
        #pragma unroll
        for (int j = 0; j < 8; j++) {
            acc[j].x += vb2.x; acc[j].y += vb2.y; acc[j].z += vb2.z; acc[j].w += vb2.w;
        }
    }
    // LN2 reduction
    #pragma unroll
    for (int j = 0; j < 8; j++) {
        float s = acc[j].x + acc[j].y + acc[j].z + acc[j].w;
        float q = acc[j].x*acc[j].x + acc[j].y*acc[j].y + acc[j].z*acc[j].z + acc[j].w*acc[j].w;
        #pragma unroll
        for (int o = 16; o > 0; o >>= 1) {
            s += __shfl_xor_sync(0xffffffffu, s, o);
            q += __shfl_xor_sync(0xffffffffu, q, o);
        }
        if (lane == 0) { redS[warp][j] = s; redQ[warp][j] = q; }
    }
    __syncthreads();
    {
        float4 vg = *(const float4*)(g2 + c0);
        float4 ve = *(const float4*)(be2 + c0);
        float4 cmax = make_float4(-FLT_MAX,-FLT_MAX,-FLT_MAX,-FLT_MAX);
        #pragma unroll
        for (int j = 0; j < 8; j++) {
            float S = redS[2*tp][j] + redS[2*tp+1][j];
            float Q = redQ[2*tp][j] + redQ[2*tp+1][j];
            float mean = S * (1.f/CP_);
            float rstd = rsqrtf(Q*(1.f/CP_) - mean*mean + 1e-5f);
            float4 lv;
            lv.x = (acc[j].x-mean)*rstd*vg.x + ve.x;
            lv.y = (acc[j].y-mean)*rstd*vg.y + ve.y;
            lv.z = (acc[j].z-mean)*rstd*vg.z + ve.z;
            lv.w = (acc[j].w-mean)*rstd*vg.w + ve.w;
            *(float4*)(d_local + ((size_t)(bv*N_ + n0) + tp*8 + j)*CP_ + c0) = lv;
            cmax.x = fmaxf(cmax.x, lv.x); cmax.y = fmaxf(cmax.y, lv.y);
            cmax.z = fmaxf(cmax.z, lv.z); cmax.w = fmaxf(cmax.w, lv.w);
        }
        *(float4*)&scmax[tp][c0] = cmax;
    }
    __syncthreads();
    {
        int c = tid;
        float m = fmaxf(fmaxf(scmax[0][c], scmax[1][c]),
                        fmaxf(scmax[2][c], scmax[3][c]));
        atomicMaxFloat(&d_gmax[bv*CP_ + c], m);
    }
}

// ---------------- kernel C: gpart = global_xyz @ W3[256:512] + b3 -----------
__global__ void __launch_bounds__(256) kC(const float* __restrict__ W3,
                                          const float* __restrict__ b3) {
    int bv = blockIdx.x;
    int c  = threadIdx.x;
    __shared__ float sg[CP_];
    sg[c] = d_gmax[bv*CP_ + c];
    __syncthreads();
    float acc = b3[c];
    const float* w = W3 + (size_t)256*CP_ + c;   // bottom half rows
    #pragma unroll 8
    for (int k = 0; k < CP_; k++) acc += sg[k] * w[(size_t)k*CP_];
    d_gpart[bv*CP_ + c] = acc;
}

// ---------------- kernel D: W3-top GEMM + LN + ReLU + W4 dot -> weights -----
__global__ void __launch_bounds__(256) kD(const float* __restrict__ masks,
    const float* __restrict__ W3, const float* __restrict__ g3,
    const float* __restrict__ be3, const float* __restrict__ W4)
{
    __shared__ __align__(16) float sh[TP_][CP_];
    __shared__ float redS[8][8];
    __shared__ float redQ[8][8];
    __shared__ float swgt[TP_];

    int tile = blockIdx.x;
    int bv = tile / TPB_;
    int n0 = (tile % TPB_) * TP_;
    int tid = threadIdx.x;
    int tc = tid & 63, tp = tid >> 6;
    int c0 = tc * 4;
    int lane = tid & 31, warp = tid >> 5;

    // cooperative coalesced load of the local tile (32x256 fp32 = 32KB)
    {
        const float4* src = (const float4*)(d_local + (size_t)(bv*N_ + n0)*CP_);
        float4* dst = (float4*)&sh[0][0];
        #pragma unroll
        for (int i = 0; i < 8; i++) dst[tid + 256*i] = src[tid + 256*i];
    }
    __syncthreads();

    float4 gp = *(const float4*)(d_gpart + bv*CP_ + c0);
    float4 acc[8];
    #pragma unroll
    for (int j = 0; j < 8; j++) acc[j] = gp;

    const float* w3p = W3 + c0;
    for (int k = 0; k < CP_; k += 4) {
        float4 wa = *(const float4*)(w3p + (size_t)(k+0)*CP_);
        float4 wb = *(const float4*)(w3p + (size_t)(k+1)*CP_);
        float4 wc = *(const float4*)(w3p + (size_t)(k+2)*CP_);
        float4 wd = *(const float4*)(w3p + (size_t)(k+3)*CP_);
        #pragma unroll
        for (int j = 0; j < 8; j++) {
            float4 h4 = *(const float4*)&sh[tp*8+j][k];
            acc[j].x += h4.x*wa.x; acc[j].y += h4.x*wa.y; acc[j].z += h4.x*wa.z; acc[j].w += h4.x*wa.w;
            acc[j].x += h4.y*wb.x; acc[j].y += h4.y*wb.y; acc[j].z += h4.y*wb.z; acc[j].w += h4.y*wb.w;
            acc[j].x += h4.z*wc.x; acc[j].y += h4.z*wc.y; acc[j].z += h4.z*wc.z; acc[j].w += h4.z*wc.w;
            acc[j].x += h4.w*wd.x; acc[j].y += h4.w*wd.y; acc[j].z += h4.w*wd.z; acc[j].w += h4.w*wd.w;
        }
    }

    // LN3 reduction
    #pragma unroll
    for (int j = 0; j < 8; j++) {
        float s = acc[j].x + acc[j].y + acc[j].z + acc[j].w;
        float q = acc[j].x*acc[j].x + acc[j].y*acc[j].y + acc[j].z*acc[j].z + acc[j].w*acc[j].w;
        #pragma unroll
        for (int o = 16; o > 0; o >>= 1) {
            s += __shfl_xor_sync(0xffffffffu, s, o);
            q += __shfl_xor_sync(0xffffffffu, q, o);
        }
        if (lane == 0) { redS[warp][j] = s; redQ[warp][j] = q; }
    }
    __syncthreads();

    float part[8];
    {
        float4 vg  = *(const float4*)(g3 + c0);
        float4 ve  = *(const float4*)(be3 + c0);
        float4 w4v = *(const float4*)(W4 + c0);
        #pragma unroll
        for (int j = 0; j < 8; j++) {
            float S = redS[2*tp][j] + redS[2*tp+1][j];
            float Q = redQ[2*tp][j] + redQ[2*tp+1][j];
            float mean = S * (1.f/CP_);
            float rstd = rsqrtf(Q*(1.f/CP_) - mean*mean + 1e-5f);
            float hx = fmaxf((acc[j].x-mean)*rstd*vg.x + ve.x, 0.f);
            float hy = fmaxf((acc[j].y-mean)*rstd*vg.y + ve.y, 0.f);
            float hz = fmaxf((acc[j].z-mean)*rstd*vg.z + ve.z, 0.f);
            float hw = fmaxf((acc[j].w-mean)*rstd*vg.w + ve.w, 0.f);
            part[j] = hx*w4v.x + hy*w4v.y + hz*w4v.z + hw*w4v.w;
        }
    }
    __syncthreads();   // protect redS reuse below

    // reduce W4 dot across the 64 threads of each point group
    #pragma unroll
    for (int j = 0; j < 8; j++) {
        float s = part[j];
        #pragma unroll
        for (int o = 16; o > 0; o >>= 1) s += __shfl_xor_sync(0xffffffffu, s, o);
        if (lane == 0) redS[warp][j] = s;
    }
    __syncthreads();

    if (tc == 0) {   // one thread per point group (tid 0,64,128,192)
        const float* mrow = masks + (size_t)bv*N_;
        #pragma unroll
        for (int j = 0; j < 8; j++) {
            float dot = redS[2*tp][j] + redS[2*tp+1][j];
            int n = n0 + tp*8 + j;
            float m = mrow[n];
            float w = 2.f * m / (1.f + expf(-dot));   // mask * sigmoid * 2
            d_mw[(size_t)bv*N_ + n] = w;
            swgt[tp*8+j] = w;
        }
    }
    __syncthreads();
    if (tid == 0) {
        float s = 0.f;
        #pragma unroll
        for (int p = 0; p < TP_; p++) s += swgt[p];
        atomicAdd(&d_denom[bv], s);
    }
}

// ---------------- kernel E: weighted pooling + epilogue ---------------------
__global__ void __launch_bounds__(256) kE(const float* __restrict__ feats,
                                          float* __restrict__ out) {
    int blk = blockIdx.x;        // b*CP_ + c
    int b = blk >> 8;
    int c = blk & 255;
    int tid = threadIdx.x;

    const float* f   = feats + (size_t)(b*CP_ + c)*N_;
    const float* mw0 = d_mw + (size_t)(b*4+0)*N_;
    const float* mw1 = d_mw + (size_t)(b*4+1)*N_;
    const float* mw2 = d_mw + (size_t)(b*4+2)*N_;
    const float* mw3 = d_mw + (size_t)(b*4+3)*N_;

    float a0=0.f, a1=0.f, a2=0.f, a3=0.f;
    for (int n = tid; n < N_; n += 256) {
        float fv = f[n];
        a0 += fv*mw0[n]; a1 += fv*mw1[n]; a2 += fv*mw2[n]; a3 += fv*mw3[n];
    }
    #pragma unroll
    for (int o = 16; o > 0; o >>= 1) {
        a0 += __shfl_xor_sync(0xffffffffu, a0, o);
        a1 += __shfl_xor_sync(0xffffffffu, a1, o);
        a2 += __shfl_xor_sync(0xffffffffu, a2, o);
        a3 += __shfl_xor_sync(0xffffffffu, a3, o);
    }
    __shared__ float sr[4][8];
    int lane = tid & 31, warp = tid >> 5;
    if (lane == 0) { sr[0][warp]=a0; sr[1][warp]=a1; sr[2][warp]=a2; sr[3][warp]=a3; }
    __syncthreads();
    if (tid < 4) {
        float p = 0.f;
        #pragma unroll
        for (int w = 0; w < 8; w++) p += sr[tid][w];
        int bvv = b*4 + tid;
        float den = fmaxf(d_denom[bvv], 1e-8f);
        out[(size_t)bvv*CP_ + c] = p/den + d_gmax[bvv*CP_ + c];
    }
}

// ---------------- launch ----------------------------------------------------
extern "C" void kernel_launch(void* const* d_in, const int* in_sizes, int n_in,
                              void* d_out, int out_size) {
    const float* xyz = (const float*)d_in[0];
    const float* pf  = (const float*)d_in[1];
    const float* pm  = (const float*)d_in[2];
    const float* W1  = (const float*)d_in[3];
    const float* b1  = (const float*)d_in[4];
    const float* g1  = (const float*)d_in[5];
    const float* be1 = (const float*)d_in[6];
    const float* W2  = (const float*)d_in[7];
    const float* b2  = (const float*)d_in[8];
    const float* g2  = (const float*)d_in[9];
    const float* be2 = (const float*)d_in[10];
    const float* W3  = (const float*)d_in[11];
    const float* b3  = (const float*)d_in[12];
    const float* g3  = (const float*)d_in[13];
    const float* be3 = (const float*)d_in[14];
    const float* W4  = (const float*)d_in[15];
    float* out = (float*)d_out;

    kA<<<BV_, 256>>>(xyz, pm);
    kB<<<NTILES_, 256>>>(xyz, W1, b1, g1, be1, W2, b2, g2, be2);
    kC<<<BV_, 256>>>(W3, b3);
    kD<<<NTILES_, 256>>>(pm, W3, g3, be3, W4);
    kE<<<B_*CP_, 256>>>(pf, out);
}